// round 4
// baseline (speedup 1.0000x reference)
#include <cuda_runtime.h>
#include <math.h>

#define NMAX 16384

// 128 MB scratch for stacked, stored block-transposed:
// stackedT[tile][k][r], tile = n/64, r = n%64, k = v*128 + o
__device__ __align__(256) float g_stackedT[(size_t)NMAX * 2048];

static __device__ __forceinline__ float eluf(float t) { return t > 0.f ? t : expm1f(t); }
static __device__ __forceinline__ float sigm(float t) { return 1.f / (1.f + expf(-t)); }

// ---- packed f32x2 helpers (Blackwell sm_100+) ----
static __device__ __forceinline__ unsigned long long pk2(float lo, float hi) {
    unsigned long long r;
    asm("mov.b64 %0, {%1, %2};" : "=l"(r) : "f"(lo), "f"(hi));
    return r;
}
static __device__ __forceinline__ void upk2(unsigned long long p, float& lo, float& hi) {
    asm("mov.b64 {%0, %1}, %2;" : "=f"(lo), "=f"(hi) : "l"(p));
}
static __device__ __forceinline__ void fma2(unsigned long long& d,
                                            unsigned long long a,
                                            unsigned long long b) {
    asm("fma.rn.f32x2 %0, %1, %2, %0;" : "+l"(d) : "l"(a), "l"(b));
}

// ---------------------------------------------------------------------------
// Stage 1: per-variable GRN + LayerNorm -> g_stackedT
// grid = (N/64, 16), 256 threads, 2 CTAs/SM.
// Thread tile: 8 rows (rt = tid&7) x 2 outputs per 64-o chunk (ot = tid>>3).
// ---------------------------------------------------------------------------
__global__ void __launch_bounds__(256, 2) vsn_stage1(
    const float* __restrict__ x,
    const float* __restrict__ W1, const float* __restrict__ b1,
    const float* __restrict__ W2, const float* __restrict__ b2,
    const float* __restrict__ Wg, const float* __restrict__ bg,
    const float* __restrict__ Ws, const float* __restrict__ bs,
    const float* __restrict__ gamma, const float* __restrict__ beta)
{
    extern __shared__ float sm[];
    float* sh_h  = sm;            // [128][68]  h transposed: [d][r]
    float* sh_w2 = sm + 8704;     // [64][132]
    float* sh_wg = sm + 17152;    // [64][132]
    float* sh_ps = sm + 25600;    // [8 warps][64 rows] partial sums
    float* sh_q  = sm + 26112;    // [8][64] partial sumsq
    float* smean = sm + 26624;    // [64]
    float* srstd = sm + 26688;    // [64]
    float* sx    = sm + 26752;    // [64]
    // total 26816 floats = 107264 B

    const int tid = threadIdx.x;
    const int rt  = tid & 7;       // rows rt*8 .. rt*8+7
    const int ot  = tid >> 3;      // 0..31 ; o = oc + ot*2 + i
    const int wrp = tid >> 5;
    const int v   = blockIdx.y;
    const int r0  = blockIdx.x * 64;

    for (int i = tid; i < 64; i += 256) sx[i] = x[(size_t)(r0 + i) * 16 + v];
    __syncthreads();

    // h[d][r] = elu(x[r]*W1[v,d] + b1[v,d])
    {
        const float* W1v = W1 + v * 128;
        const float* b1v = b1 + v * 128;
        for (int idx = tid; idx < 8192; idx += 256) {
            int r = idx & 63, d = idx >> 6;
            sh_h[d * 68 + r] = eluf(fmaf(sx[r], W1v[d], b1v[d]));
        }
    }

    float y[4][8];   // y[slot][p]: slot = chunk*2 + i, row = rt*8+p

    for (int oc = 0; oc < 128; oc += 64) {
        __syncthreads();
        const float* W2b = W2 + ((size_t)v * 128 + oc) * 128;
        const float* Wgb = Wg + ((size_t)v * 128 + oc) * 128;
        for (int idx = tid; idx < 2048; idx += 256) {
            int o = idx >> 5, dq = (idx & 31) * 4;
            float4 a = *(const float4*)(W2b + o * 128 + dq);
            float* p = sh_w2 + o * 132 + dq;
            p[0] = a.x; p[1] = a.y; p[2] = a.z; p[3] = a.w;
            float4 b = *(const float4*)(Wgb + o * 128 + dq);
            float* q = sh_wg + o * 132 + dq;
            q[0] = b.x; q[1] = b.y; q[2] = b.z; q[3] = b.w;
        }
        __syncthreads();

        unsigned long long a2[2][4], ag[2][4];
        #pragma unroll
        for (int i = 0; i < 2; i++)
            #pragma unroll
            for (int q = 0; q < 4; q++) { a2[i][q] = 0ull; ag[i][q] = 0ull; }

        #pragma unroll 4
        for (int d = 0; d < 128; d++) {
            const float* hp = sh_h + d * 68 + rt * 8;
            float4 ha = *(const float4*)hp;
            float4 hb = *(const float4*)(hp + 4);
            unsigned long long rp[4];
            rp[0] = pk2(ha.x, ha.y); rp[1] = pk2(ha.z, ha.w);
            rp[2] = pk2(hb.x, hb.y); rp[3] = pk2(hb.z, hb.w);
            #pragma unroll
            for (int i = 0; i < 2; i++) {
                float w2v = sh_w2[(ot * 2 + i) * 132 + d];
                unsigned long long w2p = pk2(w2v, w2v);
                fma2(a2[i][0], rp[0], w2p);
                fma2(a2[i][1], rp[1], w2p);
                fma2(a2[i][2], rp[2], w2p);
                fma2(a2[i][3], rp[3], w2p);
                float wgv = sh_wg[(ot * 2 + i) * 132 + d];
                unsigned long long wgp = pk2(wgv, wgv);
                fma2(ag[i][0], rp[0], wgp);
                fma2(ag[i][1], rp[1], wgp);
                fma2(ag[i][2], rp[2], wgp);
                fma2(ag[i][3], rp[3], wgp);
            }
        }

        // epilogue into registers
        #pragma unroll
        for (int i = 0; i < 2; i++) {
            int o = oc + ot * 2 + i;
            int slot = (oc >> 5) + i;   // oc/64*2 + i
            float b2v = b2[v * 128 + o];
            float bgv = bg[v * 128 + o];
            float wsv = Ws[v * 128 + o];
            float bsv = bs[v * 128 + o];
            #pragma unroll
            for (int q = 0; q < 4; q++) {
                float h2a, h2b, ga, gb;
                upk2(a2[i][q], h2a, h2b);
                upk2(ag[i][q], ga, gb);
                int p = q * 2;
                float g0 = sigm(ga + bgv);
                float g1 = sigm(gb + bgv);
                float sk0 = fmaf(sx[rt * 8 + p], wsv, bsv);
                float sk1 = fmaf(sx[rt * 8 + p + 1], wsv, bsv);
                y[slot][p]     = g0 * (h2a + b2v) + (1.f - g0) * sk0;
                y[slot][p + 1] = g1 * (h2b + b2v) + (1.f - g1) * sk1;
            }
        }
    }

    // LayerNorm: per-thread partials over its 4 o-values per row
    {
        float s[8], s2[8];
        #pragma unroll
        for (int p = 0; p < 8; p++) {
            float a = y[0][p] + y[1][p];
            float b = y[2][p] + y[3][p];
            s[p] = a + b;
            s2[p] = y[0][p] * y[0][p];
            s2[p] = fmaf(y[1][p], y[1][p], s2[p]);
            s2[p] = fmaf(y[2][p], y[2][p], s2[p]);
            s2[p] = fmaf(y[3][p], y[3][p], s2[p]);
        }
        // reduce across the 4 ot-values within a warp (lanes differ by 8, 16)
        #pragma unroll
        for (int p = 0; p < 8; p++) {
            s[p]  += __shfl_xor_sync(0xffffffffu, s[p], 8);
            s[p]  += __shfl_xor_sync(0xffffffffu, s[p], 16);
            s2[p] += __shfl_xor_sync(0xffffffffu, s2[p], 8);
            s2[p] += __shfl_xor_sync(0xffffffffu, s2[p], 16);
        }
        if ((ot & 3) == 0) {
            #pragma unroll
            for (int p = 0; p < 8; p++) {
                sh_ps[wrp * 64 + rt * 8 + p] = s[p];
                sh_q[wrp * 64 + rt * 8 + p] = s2[p];
            }
        }
    }
    __syncthreads();
    if (tid < 64) {
        float s = 0.f, s2 = 0.f;
        #pragma unroll
        for (int w = 0; w < 8; w++) { s += sh_ps[w * 64 + tid]; s2 += sh_q[w * 64 + tid]; }
        float m = s * 0.0078125f;
        float var = fmaf(-m, m, s2 * 0.0078125f);
        smean[tid] = m;
        srstd[tid] = rsqrtf(var + 1e-5f);
    }
    __syncthreads();

    // normalize in registers + write transposed to global
    {
        float mrow[8], rrow[8];
        #pragma unroll
        for (int p = 0; p < 8; p++) { mrow[p] = smean[rt * 8 + p]; rrow[p] = srstd[rt * 8 + p]; }
        float* dst = g_stackedT + ((size_t)blockIdx.x * 2048 + v * 128) * 64;
        const float* gv = gamma + v * 128;
        const float* bv = beta + v * 128;
        #pragma unroll
        for (int slot = 0; slot < 4; slot++) {
            int o = (slot >> 1) * 64 + ot * 2 + (slot & 1);
            float go = gv[o], bo = bv[o];
            float4 oa, ob;
            oa.x = fmaf((y[slot][0] - mrow[0]) * rrow[0], go, bo);
            oa.y = fmaf((y[slot][1] - mrow[1]) * rrow[1], go, bo);
            oa.z = fmaf((y[slot][2] - mrow[2]) * rrow[2], go, bo);
            oa.w = fmaf((y[slot][3] - mrow[3]) * rrow[3], go, bo);
            ob.x = fmaf((y[slot][4] - mrow[4]) * rrow[4], go, bo);
            ob.y = fmaf((y[slot][5] - mrow[5]) * rrow[5], go, bo);
            ob.z = fmaf((y[slot][6] - mrow[6]) * rrow[6], go, bo);
            ob.w = fmaf((y[slot][7] - mrow[7]) * rrow[7], go, bo);
            *(float4*)(dst + o * 64 + rt * 8) = oa;
            *(float4*)(dst + o * 64 + rt * 8 + 4) = ob;
        }
    }
}

// ---------------------------------------------------------------------------
// Stage 2: softmax GRN + weighted sum. grid = N/64, 256 threads.
// Thread tile: 8 rows (rt = tid&7) x 4 hs-outputs (jt = tid>>3, j = jt*4+i).
// ---------------------------------------------------------------------------
__global__ void __launch_bounds__(256) vsn_stage2(
    const float* __restrict__ sW1, const float* __restrict__ sb1,
    const float* __restrict__ sW2, const float* __restrict__ sb2,
    const float* __restrict__ sWg, const float* __restrict__ sbg,
    const float* __restrict__ sWs, const float* __restrict__ sbs,
    const float* __restrict__ sgamma, const float* __restrict__ sbeta,
    float* __restrict__ outp, float* __restrict__ outw)
{
    extern __shared__ float sm[];
    float* sh_f  = sm;            // [128][64] flat chunk, k-major
    float* warea = sm + 8192;     // 17024 floats, multi-use
    float* sh_ws = sm + 25216;    // [16][132]
    float* sh_sk = sm + 27328;    // [64][17]
    float* sh_z  = sm + 28416;    // [64][17]
    float* sh_w  = sm + 29504;    // [64][17]

    float* sh_w1 = warea;           // [128][133] during main GEMM
    float* sh_hs = warea;           // [64][133]  after GEMM
    float* sh_s2 = warea + 8512;    // [16][130]
    float* sh_sg = warea + 10592;   // [16][130]
    float* sh_o  = warea;           // [64][132]  pass-3 output staging

    const int tid = threadIdx.x;
    const int rt = tid & 7;         // rows rt*8 .. rt*8+7
    const int jt = tid >> 3;        // 0..31 ; j = jt*4+i
    const int v16 = jt & 15;
    const int tile = blockIdx.x;
    const size_t rowbase = (size_t)tile * 64;
    const float* fbase = g_stackedT + (size_t)tile * 2048 * 64;

    unsigned long long acc[4][4];   // [i][rowpair]
    unsigned long long accs[4];
    #pragma unroll
    for (int i = 0; i < 4; i++) {
        accs[i] = 0ull;
        #pragma unroll
        for (int q = 0; q < 4; q++) acc[i][q] = 0ull;
    }

    // ---- main GEMM: hs (64x128) and sks (64x16) over K=2048 in 16 chunks ----
    for (int c = 0; c < 16; c++) {
        __syncthreads();
        {
            const float4* src = (const float4*)(fbase + (size_t)c * 128 * 64);
            float4* dst = (float4*)sh_f;
            for (int idx = tid; idx < 2048; idx += 256) dst[idx] = src[idx];
        }
        for (int idx = tid; idx < 4096; idx += 256) {
            int j = idx >> 5, kq = (idx & 31) * 4;
            float4 a = *(const float4*)(sW1 + (size_t)j * 2048 + c * 128 + kq);
            float* p = sh_w1 + j * 133 + kq;
            p[0] = a.x; p[1] = a.y; p[2] = a.z; p[3] = a.w;
        }
        for (int idx = tid; idx < 512; idx += 256) {
            int vv = idx >> 5, kq = (idx & 31) * 4;
            float4 a = *(const float4*)(sWs + (size_t)vv * 2048 + c * 128 + kq);
            float* p = sh_ws + vv * 132 + kq;
            p[0] = a.x; p[1] = a.y; p[2] = a.z; p[3] = a.w;
        }
        __syncthreads();

        #pragma unroll 4
        for (int kk = 0; kk < 128; kk++) {
            const float* fp = sh_f + kk * 64 + rt * 8;
            float4 fa = *(const float4*)fp;
            float4 fb = *(const float4*)(fp + 4);
            unsigned long long rp[4];
            rp[0] = pk2(fa.x, fa.y); rp[1] = pk2(fa.z, fa.w);
            rp[2] = pk2(fb.x, fb.y); rp[3] = pk2(fb.z, fb.w);
            float wsv = sh_ws[v16 * 132 + kk];
            unsigned long long wsp = pk2(wsv, wsv);
            fma2(accs[0], rp[0], wsp);
            fma2(accs[1], rp[1], wsp);
            fma2(accs[2], rp[2], wsp);
            fma2(accs[3], rp[3], wsp);
            #pragma unroll
            for (int i = 0; i < 4; i++) {
                float w = sh_w1[(jt * 4 + i) * 133 + kk];
                unsigned long long wp = pk2(w, w);
                fma2(acc[i][0], rp[0], wp);
                fma2(acc[i][1], rp[1], wp);
                fma2(acc[i][2], rp[2], wp);
                fma2(acc[i][3], rp[3], wp);
            }
        }
    }
    __syncthreads();   // sh_w1 reads done; safe to overlay

    // sks -> shared (only jt<16), hs (elu) -> shared
    if (jt < 16) {
        float sbsv = sbs[v16];
        #pragma unroll
        for (int q = 0; q < 4; q++) {
            float a, b;
            upk2(accs[q], a, b);
            sh_sk[(rt * 8 + q * 2) * 17 + v16] = a + sbsv;
            sh_sk[(rt * 8 + q * 2 + 1) * 17 + v16] = b + sbsv;
        }
    }
    #pragma unroll
    for (int i = 0; i < 4; i++) {
        int jj = jt * 4 + i;
        float bb = sb1[jj];
        #pragma unroll
        for (int q = 0; q < 4; q++) {
            float a, b;
            upk2(acc[i][q], a, b);
            sh_hs[(rt * 8 + q * 2) * 133 + jj] = eluf(a + bb);
            sh_hs[(rt * 8 + q * 2 + 1) * 133 + jj] = eluf(b + bb);
        }
    }
    for (int idx = tid; idx < 512; idx += 256) {
        int vv = idx >> 5, jq = (idx & 31) * 4;
        float4 a = *(const float4*)(sW2 + vv * 128 + jq);
        float* p = sh_s2 + vv * 130 + jq;
        p[0] = a.x; p[1] = a.y; p[2] = a.z; p[3] = a.w;
        float4 b = *(const float4*)(sWg + vv * 128 + jq);
        float* q = sh_sg + vv * 130 + jq;
        q[0] = b.x; q[1] = b.y; q[2] = b.z; q[3] = b.w;
    }
    __syncthreads();

    // tiny GEMM 128 -> 16 (x2) and GRN combine: thread = (row, quarter of v's)
    {
        int q = tid & 3, r = tid >> 2;
        float a2[4] = {0.f, 0.f, 0.f, 0.f};
        float ag[4] = {0.f, 0.f, 0.f, 0.f};
        #pragma unroll 4
        for (int j = 0; j < 128; j++) {
            float hsv = sh_hs[r * 133 + j];
            #pragma unroll
            for (int i = 0; i < 4; i++) {
                a2[i] = fmaf(hsv, sh_s2[(q * 4 + i) * 130 + j], a2[i]);
                ag[i] = fmaf(hsv, sh_sg[(q * 4 + i) * 130 + j], ag[i]);
            }
        }
        #pragma unroll
        for (int i = 0; i < 4; i++) {
            int vv = q * 4 + i;
            float h2s = a2[i] + sb2[vv];
            float gs = sigm(ag[i] + sbg[vv]);
            float sk = sh_sk[r * 17 + vv];
            sh_z[r * 17 + vv] = gs * h2s + (1.f - gs) * sk;
        }
    }
    __syncthreads();

    // LN over 16 + softmax, one thread per row
    if (tid < 64) {
        float zz[16];
        float s = 0.f;
        #pragma unroll
        for (int vv = 0; vv < 16; vv++) { zz[vv] = sh_z[tid * 17 + vv]; s += zz[vv]; }
        float m = s * 0.0625f;
        float s2 = 0.f;
        #pragma unroll
        for (int vv = 0; vv < 16; vv++) { float d = zz[vv] - m; s2 = fmaf(d, d, s2); }
        float rstd = rsqrtf(s2 * 0.0625f + 1e-5f);
        float mx = -3.4e38f;
        #pragma unroll
        for (int vv = 0; vv < 16; vv++) {
            zz[vv] = fmaf((zz[vv] - m) * rstd, sgamma[vv], sbeta[vv]);
            mx = fmaxf(mx, zz[vv]);
        }
        float se = 0.f;
        #pragma unroll
        for (int vv = 0; vv < 16; vv++) { zz[vv] = expf(zz[vv] - mx); se += zz[vv]; }
        float inv = 1.f / se;
        #pragma unroll
        for (int vv = 0; vv < 16; vv++) sh_w[tid * 17 + vv] = zz[vv] * inv;
    }
    __syncthreads();

    // weights out (coalesced)
    for (int idx = tid; idx < 1024; idx += 256) {
        int r = idx >> 4, vv = idx & 15;
        outw[(rowbase + r) * 16 + vv] = sh_w[r * 17 + vv];
    }

    // ---- pass 3: processed[r][d] = sum_v stacked[r][v][d] * w[r][v] ----
    unsigned long long accp[4][4];
    #pragma unroll
    for (int i = 0; i < 4; i++)
        #pragma unroll
        for (int q = 0; q < 4; q++) accp[i][q] = 0ull;

    for (int vv = 0; vv < 16; vv++) {
        __syncthreads();
        {
            const float4* src = (const float4*)(fbase + (size_t)vv * 128 * 64);
            float4* dst = (float4*)sh_f;
            for (int idx = tid; idx < 2048; idx += 256) dst[idx] = src[idx];
        }
        __syncthreads();
        unsigned long long wp[4];
        #pragma unroll
        for (int q = 0; q < 4; q++)
            wp[q] = pk2(sh_w[(rt * 8 + q * 2) * 17 + vv],
                        sh_w[(rt * 8 + q * 2 + 1) * 17 + vv]);
        #pragma unroll
        for (int i = 0; i < 4; i++) {
            const float* fp = sh_f + (jt * 4 + i) * 64 + rt * 8;
            float4 fa = *(const float4*)fp;
            float4 fb = *(const float4*)(fp + 4);
            fma2(accp[i][0], pk2(fa.x, fa.y), wp[0]);
            fma2(accp[i][1], pk2(fa.z, fa.w), wp[1]);
            fma2(accp[i][2], pk2(fb.x, fb.y), wp[2]);
            fma2(accp[i][3], pk2(fb.z, fb.w), wp[3]);
        }
    }
    __syncthreads();
    #pragma unroll
    for (int i = 0; i < 4; i++) {
        int d = jt * 4 + i;
        #pragma unroll
        for (int q = 0; q < 4; q++) {
            float a, b;
            upk2(accp[i][q], a, b);
            sh_o[(rt * 8 + q * 2) * 132 + d] = a;
            sh_o[(rt * 8 + q * 2 + 1) * 132 + d] = b;
        }
    }
    __syncthreads();
    for (int idx = tid; idx < 2048; idx += 256) {
        int r = idx >> 5, dq = (idx & 31) * 4;
        float4 a = *(const float4*)(sh_o + r * 132 + dq);
        *(float4*)(outp + (rowbase + r) * 128 + dq) = a;
    }
}

// ---------------------------------------------------------------------------
extern "C" void kernel_launch(void* const* d_in, const int* in_sizes, int n_in,
                              void* d_out, int out_size) {
    const float* x      = (const float*)d_in[0];
    const float* W1     = (const float*)d_in[1];
    const float* b1     = (const float*)d_in[2];
    const float* W2     = (const float*)d_in[3];
    const float* b2     = (const float*)d_in[4];
    const float* Wg     = (const float*)d_in[5];
    const float* bg     = (const float*)d_in[6];
    const float* Ws     = (const float*)d_in[7];
    const float* bs     = (const float*)d_in[8];
    const float* gamma  = (const float*)d_in[9];
    const float* beta   = (const float*)d_in[10];
    const float* sW1    = (const float*)d_in[11];
    const float* sb1    = (const float*)d_in[12];
    const float* sW2    = (const float*)d_in[13];
    const float* sb2    = (const float*)d_in[14];
    const float* sWg    = (const float*)d_in[15];
    const float* sbg    = (const float*)d_in[16];
    const float* sWs    = (const float*)d_in[17];
    const float* sbs    = (const float*)d_in[18];
    const float* sgamma = (const float*)d_in[19];
    const float* sbeta  = (const float*)d_in[20];

    int N = in_sizes[0] / 16;          // 16384 rows
    int tiles = N / 64;                // 256

    float* outp = (float*)d_out;
    float* outw = outp + (size_t)N * 128;

    cudaFuncSetAttribute(vsn_stage1, cudaFuncAttributeMaxDynamicSharedMemorySize, 107264);
    cudaFuncSetAttribute(vsn_stage2, cudaFuncAttributeMaxDynamicSharedMemorySize, 122368);

    dim3 g1(tiles, 16);
    vsn_stage1<<<g1, 256, 107264>>>(x, W1, b1, W2, b2, Wg, bg, Ws, bs, gamma, beta);
    vsn_stage2<<<tiles, 256, 122368>>>(sW1, sb1, sW2, sb2, sWg, sbg, sWs, sbs,
                                       sgamma, sbeta, outp, outw);
}